// round 14
// baseline (speedup 1.0000x reference)
#include <cuda_runtime.h>

#define NUM_CODES 1024
#define TPB 128          // 4 warps; each warp owns an independent 32-row tile
#define HPAD 5           // each hist bin on its own 128B line
#define WROWS 32         // rows per warp-tile
#define NTILES 16384     // B / WROWS (524288 / 32)
#define PFDIST 3552      // warp-tiles one residency wave ahead (888 blocks x 4)

__device__ int g_hist[NUM_CODES << HPAD];   // zero at load
__device__ unsigned int g_done;             // zero at load

// ---------------------------------------------------------------------------
// Warp-independent pipelines (R11 base) + L2 bulk prefetch one wave ahead.
// Each warp stages its own 8KB sub-tile with cp.async (mostly L2 hits thanks
// to the prefetch), computes 32 rows thread-per-row, streams out with plain
// STG.128 (L2 write buffering). No __syncthreads in the hot path.
// ---------------------------------------------------------------------------
__global__ __launch_bounds__(TPB, 6) void fsq_main(
    const float* __restrict__ ze,    // (B, 64)
    const float* __restrict__ Win,   // (4, 64) row-major
    const float4* __restrict__ Wout4,// (64) float4 rows
    float* __restrict__ zq,          // (B, 64)
    float* __restrict__ idx_out,     // (B,)
    float* __restrict__ scal,        // 4 scalars
    float invB)
{
    __shared__ float4 tile[4][WROWS * 16];   // 4 x 8KB swizzled sub-tiles
    __shared__ float  sWin[256];             // 4 x 64
    __shared__ float4 sC[4][WROWS];          // centered codes per warp
    __shared__ bool   isLast;
    __shared__ float  red[8];

    const int t    = threadIdx.x;
    const int lane = t & 31;
    const int warp = t >> 5;

    #pragma unroll
    for (int i = t; i < 256; i += TPB) sWin[i] = Win[i];
    __syncthreads();                         // weights visible to all warps

    const unsigned int warpTile = (unsigned int)blockIdx.x * 4 + warp;
    const unsigned int rowBase  = warpTile * WROWS;

    // ---- L2 prefetch: this warp's tile one residency-wave in the future ----
    if (lane == 0) {
        unsigned int pf = warpTile + PFDIST;
        if (pf < NTILES) {
            const float* pfa = ze + (size_t)pf * (WROWS * 64);
            asm volatile("cp.async.bulk.prefetch.L2.global [%0], %1;"
                         :: "l"(pfa), "r"((unsigned int)(WROWS * 256)) : "memory");
        }
    }

    // ---- stage in (per warp): 32 rows x 16 float4 via cp.async.cg ----
    const float4* gin = reinterpret_cast<const float4*>(ze) + (size_t)rowBase * 16;
    #pragma unroll
    for (int i = 0; i < 16; i++) {
        int f = lane + i * 32;               // float4 index within warp-tile
        int r = f >> 4, c = f & 15;
        int slot = (r << 4) | (c ^ (r & 7)); // conflict-free swizzle
        unsigned int dst = (unsigned int)__cvta_generic_to_shared(&tile[warp][slot]);
        asm volatile("cp.async.cg.shared.global [%0], [%1], 16;\n"
                     :: "r"(dst), "l"(gin + f) : "memory");
    }
    asm volatile("cp.async.commit_group;\n" ::: "memory");
    asm volatile("cp.async.wait_group 0;\n" ::: "memory");
    __syncwarp();

    // ---- compute: lane owns row (rowBase + lane) ----
    {
        const float4* w0 = reinterpret_cast<const float4*>(sWin);
        const float4* w1 = reinterpret_cast<const float4*>(sWin + 64);
        const float4* w2 = reinterpret_cast<const float4*>(sWin + 128);
        const float4* w3 = reinterpret_cast<const float4*>(sWin + 192);
        const int rbase = lane << 4;
        const int rx    = lane & 7;

        float a0 = 0.f, a1 = 0.f, a2 = 0.f, a3 = 0.f;
        #pragma unroll
        for (int k = 0; k < 16; k++) {
            float4 v  = tile[warp][rbase | (k ^ rx)];
            float4 x0 = w0[k], x1 = w1[k], x2 = w2[k], x3 = w3[k];
            a0 = fmaf(v.x, x0.x, fmaf(v.y, x0.y, fmaf(v.z, x0.z, fmaf(v.w, x0.w, a0))));
            a1 = fmaf(v.x, x1.x, fmaf(v.y, x1.y, fmaf(v.z, x1.z, fmaf(v.w, x1.w, a1))));
            a2 = fmaf(v.x, x2.x, fmaf(v.y, x2.y, fmaf(v.z, x2.z, fmaf(v.w, x2.w, a2))));
            a3 = fmaf(v.x, x3.x, fmaf(v.y, x3.y, fmaf(v.z, x3.z, fmaf(v.w, x3.w, a3))));
        }

        // FSQ quantize: levels (8,8,8,2), strides (1,8,64,512)
        const float acc[4] = {a0, a1, a2, a3};
        const float Lm1[4] = {7.f, 7.f, 7.f, 1.f};
        const int   str[4] = {1, 8, 64, 512};
        float c[4];
        int index = 0;
        #pragma unroll
        for (int j = 0; j < 4; j++) {
            float u = (tanhf(acc[j]) + 1.0f) * 0.5f;
            float s = u * Lm1[j];
            float r = rintf(s);                       // round-half-even == jnp.round
            r = fminf(fmaxf(r, 0.0f), Lm1[j]);
            index += (int)r * str[j];
            c[j] = r - Lm1[j] * 0.5f;
        }

        __stcs(&idx_out[rowBase + lane], (float)index);  // coalesced STG.32
        atomicAdd(&g_hist[index << HPAD], 1);            // 1 bin per 128B line

        sC[warp][lane] = make_float4(c[0], c[1], c[2], c[3]);
    }
    __syncwarp();

    // ---- stage out (per warp): regenerate outputs, coalesced, plain STG ----
    // f = lane + 32*i: column group f&15 == lane&15 (constant), row f>>4 varies.
    {
        const int cgrp = lane & 15;
        const float4 q0 = Wout4[4 * cgrp + 0];
        const float4 q1 = Wout4[4 * cgrp + 1];
        const float4 q2 = Wout4[4 * cgrp + 2];
        const float4 q3 = Wout4[4 * cgrp + 3];

        float4* gout = reinterpret_cast<float4*>(zq) + (size_t)rowBase * 16;
        #pragma unroll
        for (int i = 0; i < 16; i++) {
            int f = lane + i * 32;
            int r = f >> 4;
            float4 cr = sC[warp][r];           // broadcast LDS.128 (2 rows/warp)
            float4 o;
            o.x = fmaf(cr.x, q0.x, fmaf(cr.y, q0.y, fmaf(cr.z, q0.z, cr.w * q0.w)));
            o.y = fmaf(cr.x, q1.x, fmaf(cr.y, q1.y, fmaf(cr.z, q1.z, cr.w * q1.w)));
            o.z = fmaf(cr.x, q2.x, fmaf(cr.y, q2.y, fmaf(cr.z, q2.z, cr.w * q2.w)));
            o.w = fmaf(cr.x, q3.x, fmaf(cr.y, q3.y, fmaf(cr.z, q3.z, cr.w * q3.w)));
            gout[f] = o;                       // default policy: L2 write buffering
        }
    }

    // ---- last-block finalize (fused; no second launch) ----
    __threadfence();       // make this thread's hist REDs globally visible
    __syncthreads();       // all warps of this block done + fenced
    if (t == 0) {
        unsigned int v = atomicAdd(&g_done, 1u);
        isLast = (v == gridDim.x - 1);
    }
    __syncthreads();
    if (!isLast) return;

    __threadfence();   // acquire: all blocks' hist atomics visible
    float term = 0.f, nz = 0.f;
    #pragma unroll
    for (int i = t; i < NUM_CODES; i += TPB) {
        int cnt = g_hist[i << HPAD];
        g_hist[i << HPAD] = 0;                        // reset for next replay
        float p = (float)cnt * invB;
        term += p * logf(p + 1e-10f);
        nz   += (cnt > 0) ? 1.0f : 0.0f;
    }
    #pragma unroll
    for (int o = 16; o > 0; o >>= 1) {
        term += __shfl_down_sync(0xFFFFFFFFu, term, o);
        nz   += __shfl_down_sync(0xFFFFFFFFu, nz, o);
    }
    if ((t & 31) == 0) { red[t >> 5] = term; red[4 + (t >> 5)] = nz; }
    __syncthreads();
    if (t == 0) {
        float s = red[0] + red[1] + red[2] + red[3];
        float n = red[4] + red[5] + red[6] + red[7];
        scal[0] = 0.0f;                  // commitment_loss
        scal[1] = 0.0f;                  // codebook_loss
        scal[2] = expf(-s);              // perplexity
        scal[3] = n * (1.0f / 1024.0f);  // utilization
        g_done = 0;                      // reset for next replay
    }
}

// ---------------------------------------------------------------------------
extern "C" void kernel_launch(void* const* d_in, const int* in_sizes, int n_in,
                              void* d_out, int out_size) {
    const float* ze   = (const float*)d_in[0];  // (B, 64)
    const float* Win  = (const float*)d_in[1];  // (4, 64)
    const float* Wout = (const float*)d_in[2];  // (64, 4)

    const int B = in_sizes[0] / 64;
    float* out  = (float*)d_out;
    float* zq   = out;                       // B*64
    float* idxf = out + (size_t)B * 64;      // B
    float* scal = idxf + B;                  // 4 scalars

    const int grid = B / TPB;                // 524288 / 128 = 4096

    fsq_main<<<grid, TPB>>>(ze, Win, (const float4*)Wout,
                            zq, idxf, scal, 1.0f / (float)B);
}

// round 15
// speedup vs baseline: 1.0474x; 1.0474x over previous
#include <cuda_runtime.h>

#define NUM_CODES 1024
#define TPB 128          // 4 warps; each warp owns an independent 32-row tile
#define HPAD 5           // each hist bin on its own 128B line
#define WROWS 32         // rows per warp-tile
#define NTILES 16384     // B / WROWS (524288 / 32)
#define PFDIST 3552      // warp-tiles one residency wave ahead (888 blocks x 4)

__device__ int g_hist[NUM_CODES << HPAD];   // zero at load
__device__ unsigned int g_done;             // zero at load

// ---------------------------------------------------------------------------
// R11 base (best) + L2 bulk prefetch one wave ahead, WITH streaming stores
// (__stcs) so the write stream does not allocate in L2 and evict the
// prefetched read lines (R14's failure mode).
// Warp-independent pipelines: each warp stages its own 8KB sub-tile with
// cp.async, waits on its own group (__syncwarp only), computes 32 rows
// thread-per-row, and streams out. No __syncthreads in the hot path.
// ---------------------------------------------------------------------------
__global__ __launch_bounds__(TPB, 6) void fsq_main(
    const float* __restrict__ ze,    // (B, 64)
    const float* __restrict__ Win,   // (4, 64) row-major
    const float4* __restrict__ Wout4,// (64) float4 rows
    float* __restrict__ zq,          // (B, 64)
    float* __restrict__ idx_out,     // (B,)
    float* __restrict__ scal,        // 4 scalars
    float invB)
{
    __shared__ float4 tile[4][WROWS * 16];   // 4 x 8KB swizzled sub-tiles
    __shared__ float  sWin[256];             // 4 x 64
    __shared__ float4 sC[4][WROWS];          // centered codes per warp
    __shared__ bool   isLast;
    __shared__ float  red[8];

    const int t    = threadIdx.x;
    const int lane = t & 31;
    const int warp = t >> 5;

    #pragma unroll
    for (int i = t; i < 256; i += TPB) sWin[i] = Win[i];
    __syncthreads();                         // weights visible to all warps

    const unsigned int warpTile = (unsigned int)blockIdx.x * 4 + warp;
    const unsigned int rowBase  = warpTile * WROWS;

    // ---- L2 prefetch: this warp's tile one residency-wave in the future ----
    if (lane == 0) {
        unsigned int pf = warpTile + PFDIST;
        if (pf < NTILES) {
            const float* pfa = ze + (size_t)pf * (WROWS * 64);
            asm volatile("cp.async.bulk.prefetch.L2.global [%0], %1;"
                         :: "l"(pfa), "r"((unsigned int)(WROWS * 256)) : "memory");
        }
    }

    // ---- stage in (per warp): 32 rows x 16 float4 via cp.async.cg ----
    const float4* gin = reinterpret_cast<const float4*>(ze) + (size_t)rowBase * 16;
    #pragma unroll
    for (int i = 0; i < 16; i++) {
        int f = lane + i * 32;               // float4 index within warp-tile
        int r = f >> 4, c = f & 15;
        int slot = (r << 4) | (c ^ (r & 7)); // conflict-free swizzle
        unsigned int dst = (unsigned int)__cvta_generic_to_shared(&tile[warp][slot]);
        asm volatile("cp.async.cg.shared.global [%0], [%1], 16;\n"
                     :: "r"(dst), "l"(gin + f) : "memory");
    }
    asm volatile("cp.async.commit_group;\n" ::: "memory");
    asm volatile("cp.async.wait_group 0;\n" ::: "memory");
    __syncwarp();

    // ---- compute: lane owns row (rowBase + lane) ----
    {
        const float4* w0 = reinterpret_cast<const float4*>(sWin);
        const float4* w1 = reinterpret_cast<const float4*>(sWin + 64);
        const float4* w2 = reinterpret_cast<const float4*>(sWin + 128);
        const float4* w3 = reinterpret_cast<const float4*>(sWin + 192);
        const int rbase = lane << 4;
        const int rx    = lane & 7;

        float a0 = 0.f, a1 = 0.f, a2 = 0.f, a3 = 0.f;
        #pragma unroll
        for (int k = 0; k < 16; k++) {
            float4 v  = tile[warp][rbase | (k ^ rx)];
            float4 x0 = w0[k], x1 = w1[k], x2 = w2[k], x3 = w3[k];
            a0 = fmaf(v.x, x0.x, fmaf(v.y, x0.y, fmaf(v.z, x0.z, fmaf(v.w, x0.w, a0))));
            a1 = fmaf(v.x, x1.x, fmaf(v.y, x1.y, fmaf(v.z, x1.z, fmaf(v.w, x1.w, a1))));
            a2 = fmaf(v.x, x2.x, fmaf(v.y, x2.y, fmaf(v.z, x2.z, fmaf(v.w, x2.w, a2))));
            a3 = fmaf(v.x, x3.x, fmaf(v.y, x3.y, fmaf(v.z, x3.z, fmaf(v.w, x3.w, a3))));
        }

        // FSQ quantize: levels (8,8,8,2), strides (1,8,64,512)
        const float acc[4] = {a0, a1, a2, a3};
        const float Lm1[4] = {7.f, 7.f, 7.f, 1.f};
        const int   str[4] = {1, 8, 64, 512};
        float c[4];
        int index = 0;
        #pragma unroll
        for (int j = 0; j < 4; j++) {
            float u = (tanhf(acc[j]) + 1.0f) * 0.5f;
            float s = u * Lm1[j];
            float r = rintf(s);                       // round-half-even == jnp.round
            r = fminf(fmaxf(r, 0.0f), Lm1[j]);
            index += (int)r * str[j];
            c[j] = r - Lm1[j] * 0.5f;
        }

        __stcs(&idx_out[rowBase + lane], (float)index);  // coalesced STG.32
        atomicAdd(&g_hist[index << HPAD], 1);            // 1 bin per 128B line

        sC[warp][lane] = make_float4(c[0], c[1], c[2], c[3]);
    }
    __syncwarp();

    // ---- stage out (per warp): regenerate outputs, coalesced, STREAMING ----
    // f = lane + 32*i: column group f&15 == lane&15 (constant), row f>>4 varies.
    {
        const int cgrp = lane & 15;
        const float4 q0 = Wout4[4 * cgrp + 0];
        const float4 q1 = Wout4[4 * cgrp + 1];
        const float4 q2 = Wout4[4 * cgrp + 2];
        const float4 q3 = Wout4[4 * cgrp + 3];

        float4* gout = reinterpret_cast<float4*>(zq) + (size_t)rowBase * 16;
        #pragma unroll
        for (int i = 0; i < 16; i++) {
            int f = lane + i * 32;
            int r = f >> 4;
            float4 cr = sC[warp][r];           // broadcast LDS.128 (2 rows/warp)
            float4 o;
            o.x = fmaf(cr.x, q0.x, fmaf(cr.y, q0.y, fmaf(cr.z, q0.z, cr.w * q0.w)));
            o.y = fmaf(cr.x, q1.x, fmaf(cr.y, q1.y, fmaf(cr.z, q1.z, cr.w * q1.w)));
            o.z = fmaf(cr.x, q2.x, fmaf(cr.y, q2.y, fmaf(cr.z, q2.z, cr.w * q2.w)));
            o.w = fmaf(cr.x, q3.x, fmaf(cr.y, q3.y, fmaf(cr.z, q3.z, cr.w * q3.w)));
            __stcs(&gout[f], o);               // evict-first: keep L2 for reads
        }
    }

    // ---- last-block finalize (fused; no second launch) ----
    __threadfence();       // make this thread's hist REDs globally visible
    __syncthreads();       // all warps of this block done + fenced
    if (t == 0) {
        unsigned int v = atomicAdd(&g_done, 1u);
        isLast = (v == gridDim.x - 1);
    }
    __syncthreads();
    if (!isLast) return;

    __threadfence();   // acquire: all blocks' hist atomics visible
    float term = 0.f, nz = 0.f;
    #pragma unroll
    for (int i = t; i < NUM_CODES; i += TPB) {
        int cnt = g_hist[i << HPAD];
        g_hist[i << HPAD] = 0;                        // reset for next replay
        float p = (float)cnt * invB;
        term += p * logf(p + 1e-10f);
        nz   += (cnt > 0) ? 1.0f : 0.0f;
    }
    #pragma unroll
    for (int o = 16; o > 0; o >>= 1) {
        term += __shfl_down_sync(0xFFFFFFFFu, term, o);
        nz   += __shfl_down_sync(0xFFFFFFFFu, nz, o);
    }
    if ((t & 31) == 0) { red[t >> 5] = term; red[4 + (t >> 5)] = nz; }
    __syncthreads();
    if (t == 0) {
        float s = red[0] + red[1] + red[2] + red[3];
        float n = red[4] + red[5] + red[6] + red[7];
        scal[0] = 0.0f;                  // commitment_loss
        scal[1] = 0.0f;                  // codebook_loss
        scal[2] = expf(-s);              // perplexity
        scal[3] = n * (1.0f / 1024.0f);  // utilization
        g_done = 0;                      // reset for next replay
    }
}

// ---------------------------------------------------------------------------
extern "C" void kernel_launch(void* const* d_in, const int* in_sizes, int n_in,
                              void* d_out, int out_size) {
    const float* ze   = (const float*)d_in[0];  // (B, 64)
    const float* Win  = (const float*)d_in[1];  // (4, 64)
    const float* Wout = (const float*)d_in[2];  // (64, 4)

    const int B = in_sizes[0] / 64;
    float* out  = (float*)d_out;
    float* zq   = out;                       // B*64
    float* idxf = out + (size_t)B * 64;      // B
    float* scal = idxf + B;                  // 4 scalars

    const int grid = B / TPB;                // 524288 / 128 = 4096

    fsq_main<<<grid, TPB>>>(ze, Win, (const float4*)Wout,
                            zq, idxf, scal, 1.0f / (float)B);
}

// round 16
// speedup vs baseline: 1.1557x; 1.1034x over previous
#include <cuda_runtime.h>

#define NUM_CODES 1024
#define TPB 128          // 4 warps; each warp owns an independent 32-row tile
#define HPAD 5           // each hist bin on its own 128B line
#define WROWS 32         // rows per warp-tile

__device__ int g_hist[NUM_CODES << HPAD];   // zero at load
__device__ unsigned int g_done;             // zero at load

// ---------------------------------------------------------------------------
// R11 base + split-tile intra-warp pipelining. Each warp stages its 8KB tile
// as TWO cp.async groups (rows 0-15, 16-31). After wait_group 1 all 32 lanes
// compute the first half (lane pair l/l+16 splits row l&15, combined with 4
// shfl_xor(16)), hiding the second group's DRAM latency behind compute.
// No __syncthreads in the hot path.
// ---------------------------------------------------------------------------
__global__ __launch_bounds__(TPB, 6) void fsq_main(
    const float* __restrict__ ze,    // (B, 64)
    const float* __restrict__ Win,   // (4, 64) row-major
    const float4* __restrict__ Wout4,// (64) float4 rows
    float* __restrict__ zq,          // (B, 64)
    float* __restrict__ idx_out,     // (B,)
    float* __restrict__ scal,        // 4 scalars
    float invB)
{
    __shared__ float4 tile[4][WROWS * 16];   // 4 x 8KB swizzled sub-tiles
    __shared__ float  sWin[256];             // 4 x 64
    __shared__ float4 sC[4][WROWS];          // centered codes per warp
    __shared__ bool   isLast;
    __shared__ float  red[8];

    const int t    = threadIdx.x;
    const int lane = t & 31;
    const int warp = t >> 5;

    #pragma unroll
    for (int i = t; i < 256; i += TPB) sWin[i] = Win[i];
    __syncthreads();                         // weights visible to all warps

    const unsigned int rowBase =
        ((unsigned int)blockIdx.x * 4 + warp) * WROWS;
    const float4* gin = reinterpret_cast<const float4*>(ze) + (size_t)rowBase * 16;

    // ---- stage in: two 4KB cp.async groups (rows 0-15, then 16-31) ----
    #pragma unroll
    for (int i = 0; i < 8; i++) {
        int f = lane + i * 32;               // rows 0..15
        int r = f >> 4, c = f & 15;
        int slot = (r << 4) | (c ^ (r & 7));
        unsigned int dst = (unsigned int)__cvta_generic_to_shared(&tile[warp][slot]);
        asm volatile("cp.async.cg.shared.global [%0], [%1], 16;\n"
                     :: "r"(dst), "l"(gin + f) : "memory");
    }
    asm volatile("cp.async.commit_group;\n" ::: "memory");
    #pragma unroll
    for (int i = 8; i < 16; i++) {
        int f = lane + i * 32;               // rows 16..31
        int r = f >> 4, c = f & 15;
        int slot = (r << 4) | (c ^ (r & 7));
        unsigned int dst = (unsigned int)__cvta_generic_to_shared(&tile[warp][slot]);
        asm volatile("cp.async.cg.shared.global [%0], [%1], 16;\n"
                     :: "r"(dst), "l"(gin + f) : "memory");
    }
    asm volatile("cp.async.commit_group;\n" ::: "memory");

    // ---- compute halves: lane pair (l, l+16) splits row (half*16 + (l&15)) ----
    const float4* w0 = reinterpret_cast<const float4*>(sWin);
    const float4* w1 = reinterpret_cast<const float4*>(sWin + 64);
    const float4* w2 = reinterpret_cast<const float4*>(sWin + 128);
    const float4* w3 = reinterpret_cast<const float4*>(sWin + 192);
    const int r16  = lane & 15;
    const int koff = (lane >> 4) * 8;        // 0: chunks 0-7, 1: chunks 8-15

    #pragma unroll
    for (int h = 0; h < 2; ++h) {
        if (h == 0) {
            asm volatile("cp.async.wait_group 1;\n" ::: "memory");  // rows 0-15
        } else {
            asm volatile("cp.async.wait_group 0;\n" ::: "memory");  // rows 16-31
        }
        __syncwarp();

        const int row = h * 16 + r16;        // row within tile
        const int rx  = row & 7;

        float a0 = 0.f, a1 = 0.f, a2 = 0.f, a3 = 0.f;
        #pragma unroll
        for (int i = 0; i < 8; i++) {
            int k = i + koff;
            float4 v  = tile[warp][(row << 4) | (k ^ rx)];
            float4 x0 = w0[k], x1 = w1[k], x2 = w2[k], x3 = w3[k];
            a0 = fmaf(v.x, x0.x, fmaf(v.y, x0.y, fmaf(v.z, x0.z, fmaf(v.w, x0.w, a0))));
            a1 = fmaf(v.x, x1.x, fmaf(v.y, x1.y, fmaf(v.z, x1.z, fmaf(v.w, x1.w, a1))));
            a2 = fmaf(v.x, x2.x, fmaf(v.y, x2.y, fmaf(v.z, x2.z, fmaf(v.w, x2.w, a2))));
            a3 = fmaf(v.x, x3.x, fmaf(v.y, x3.y, fmaf(v.z, x3.z, fmaf(v.w, x3.w, a3))));
        }
        // combine half-rows: both lanes of the pair end with full sums
        a0 += __shfl_xor_sync(0xFFFFFFFFu, a0, 16);
        a1 += __shfl_xor_sync(0xFFFFFFFFu, a1, 16);
        a2 += __shfl_xor_sync(0xFFFFFFFFu, a2, 16);
        a3 += __shfl_xor_sync(0xFFFFFFFFu, a3, 16);

        // FSQ quantize: levels (8,8,8,2), strides (1,8,64,512)
        const float acc[4] = {a0, a1, a2, a3};
        const float Lm1[4] = {7.f, 7.f, 7.f, 1.f};
        const int   str[4] = {1, 8, 64, 512};
        float c[4];
        int index = 0;
        #pragma unroll
        for (int j = 0; j < 4; j++) {
            float u = (tanhf(acc[j]) + 1.0f) * 0.5f;
            float s = u * Lm1[j];
            float r = rintf(s);                       // round-half-even == jnp.round
            r = fminf(fmaxf(r, 0.0f), Lm1[j]);
            index += (int)r * str[j];
            c[j] = r - Lm1[j] * 0.5f;
        }

        if (lane < 16) {                              // one lane per row
            __stcs(&idx_out[rowBase + row], (float)index);
            atomicAdd(&g_hist[index << HPAD], 1);
            sC[warp][row] = make_float4(c[0], c[1], c[2], c[3]);
        }
    }
    __syncwarp();

    // ---- stage out (per warp): regenerate outputs, coalesced, streaming ----
    // f = lane + 32*i: column group f&15 == lane&15 (constant), row f>>4 varies.
    {
        const int cgrp = lane & 15;
        const float4 q0 = Wout4[4 * cgrp + 0];
        const float4 q1 = Wout4[4 * cgrp + 1];
        const float4 q2 = Wout4[4 * cgrp + 2];
        const float4 q3 = Wout4[4 * cgrp + 3];

        float4* gout = reinterpret_cast<float4*>(zq) + (size_t)rowBase * 16;
        #pragma unroll
        for (int i = 0; i < 16; i++) {
            int f = lane + i * 32;
            int r = f >> 4;
            float4 cr = sC[warp][r];           // broadcast LDS.128 (2 rows/warp)
            float4 o;
            o.x = fmaf(cr.x, q0.x, fmaf(cr.y, q0.y, fmaf(cr.z, q0.z, cr.w * q0.w)));
            o.y = fmaf(cr.x, q1.x, fmaf(cr.y, q1.y, fmaf(cr.z, q1.z, cr.w * q1.w)));
            o.z = fmaf(cr.x, q2.x, fmaf(cr.y, q2.y, fmaf(cr.z, q2.z, cr.w * q2.w)));
            o.w = fmaf(cr.x, q3.x, fmaf(cr.y, q3.y, fmaf(cr.z, q3.z, cr.w * q3.w)));
            __stcs(&gout[f], o);
        }
    }

    // ---- last-block finalize (fused; no second launch) ----
    __threadfence();       // make this thread's hist REDs globally visible
    __syncthreads();       // all warps of this block done + fenced
    if (t == 0) {
        unsigned int v = atomicAdd(&g_done, 1u);
        isLast = (v == gridDim.x - 1);
    }
    __syncthreads();
    if (!isLast) return;

    __threadfence();   // acquire: all blocks' hist atomics visible
    float term = 0.f, nz = 0.f;
    #pragma unroll
    for (int i = t; i < NUM_CODES; i += TPB) {
        int cnt = g_hist[i << HPAD];
        g_hist[i << HPAD] = 0;                        // reset for next replay
        float p = (float)cnt * invB;
        term += p * logf(p + 1e-10f);
        nz   += (cnt > 0) ? 1.0f : 0.0f;
    }
    #pragma unroll
    for (int o = 16; o > 0; o >>= 1) {
        term += __shfl_down_sync(0xFFFFFFFFu, term, o);
        nz   += __shfl_down_sync(0xFFFFFFFFu, nz, o);
    }
    if ((t & 31) == 0) { red[t >> 5] = term; red[4 + (t >> 5)] = nz; }
    __syncthreads();
    if (t == 0) {
        float s = red[0] + red[1] + red[2] + red[3];
        float n = red[4] + red[5] + red[6] + red[7];
        scal[0] = 0.0f;                  // commitment_loss
        scal[1] = 0.0f;                  // codebook_loss
        scal[2] = expf(-s);              // perplexity
        scal[3] = n * (1.0f / 1024.0f);  // utilization
        g_done = 0;                      // reset for next replay
    }
}

// ---------------------------------------------------------------------------
extern "C" void kernel_launch(void* const* d_in, const int* in_sizes, int n_in,
                              void* d_out, int out_size) {
    const float* ze   = (const float*)d_in[0];  // (B, 64)
    const float* Win  = (const float*)d_in[1];  // (4, 64)
    const float* Wout = (const float*)d_in[2];  // (64, 4)

    const int B = in_sizes[0] / 64;
    float* out  = (float*)d_out;
    float* zq   = out;                       // B*64
    float* idxf = out + (size_t)B * 64;      // B
    float* scal = idxf + B;                  // 4 scalars

    const int grid = B / TPB;                // 524288 / 128 = 4096

    fsq_main<<<grid, TPB>>>(ze, Win, (const float4*)Wout,
                            zq, idxf, scal, 1.0f / (float)B);
}

// round 17
// speedup vs baseline: 1.1628x; 1.0062x over previous
#include <cuda_runtime.h>

#define NUM_CODES 1024
#define TPB 128          // 4 warps; each warp owns an independent 32-row tile
#define HPAD 5           // each hist bin on its own 128B line
#define WROWS 32         // rows per warp-tile

__device__ int g_hist[NUM_CODES << HPAD];   // zero at load
__device__ unsigned int g_done;             // zero at load

// ---------------------------------------------------------------------------
// R11 champion structure, single change: PLAIN global stores (write-allocate)
// instead of __stcs, letting L2 aggregate the write stream into efficient
// DRAM bursts (R14 showed +5pt bus utilization with plain stores).
// Warp-independent pipelines: each warp stages its own 8KB sub-tile with
// cp.async, waits on its own group (__syncwarp only), computes 32 rows
// thread-per-row, and streams out. No __syncthreads in the hot path.
// ---------------------------------------------------------------------------
__global__ __launch_bounds__(TPB, 6) void fsq_main(
    const float* __restrict__ ze,    // (B, 64)
    const float* __restrict__ Win,   // (4, 64) row-major
    const float4* __restrict__ Wout4,// (64) float4 rows
    float* __restrict__ zq,          // (B, 64)
    float* __restrict__ idx_out,     // (B,)
    float* __restrict__ scal,        // 4 scalars
    float invB)
{
    __shared__ float4 tile[4][WROWS * 16];   // 4 x 8KB swizzled sub-tiles
    __shared__ float  sWin[256];             // 4 x 64
    __shared__ float4 sC[4][WROWS];          // centered codes per warp
    __shared__ bool   isLast;
    __shared__ float  red[8];

    const int t    = threadIdx.x;
    const int lane = t & 31;
    const int warp = t >> 5;

    #pragma unroll
    for (int i = t; i < 256; i += TPB) sWin[i] = Win[i];
    __syncthreads();                         // weights visible to all warps

    const unsigned int rowBase =
        ((unsigned int)blockIdx.x * 4 + warp) * WROWS;

    // ---- stage in (per warp): 32 rows x 16 float4 via cp.async.cg ----
    const float4* gin = reinterpret_cast<const float4*>(ze) + (size_t)rowBase * 16;
    #pragma unroll
    for (int i = 0; i < 16; i++) {
        int f = lane + i * 32;               // float4 index within warp-tile
        int r = f >> 4, c = f & 15;
        int slot = (r << 4) | (c ^ (r & 7)); // conflict-free swizzle
        unsigned int dst = (unsigned int)__cvta_generic_to_shared(&tile[warp][slot]);
        asm volatile("cp.async.cg.shared.global [%0], [%1], 16;\n"
                     :: "r"(dst), "l"(gin + f) : "memory");
    }
    asm volatile("cp.async.commit_group;\n" ::: "memory");
    asm volatile("cp.async.wait_group 0;\n" ::: "memory");
    __syncwarp();

    // ---- compute: lane owns row (rowBase + lane) ----
    {
        const float4* w0 = reinterpret_cast<const float4*>(sWin);
        const float4* w1 = reinterpret_cast<const float4*>(sWin + 64);
        const float4* w2 = reinterpret_cast<const float4*>(sWin + 128);
        const float4* w3 = reinterpret_cast<const float4*>(sWin + 192);
        const int rbase = lane << 4;
        const int rx    = lane & 7;

        float a0 = 0.f, a1 = 0.f, a2 = 0.f, a3 = 0.f;
        #pragma unroll
        for (int k = 0; k < 16; k++) {
            float4 v  = tile[warp][rbase | (k ^ rx)];
            float4 x0 = w0[k], x1 = w1[k], x2 = w2[k], x3 = w3[k];
            a0 = fmaf(v.x, x0.x, fmaf(v.y, x0.y, fmaf(v.z, x0.z, fmaf(v.w, x0.w, a0))));
            a1 = fmaf(v.x, x1.x, fmaf(v.y, x1.y, fmaf(v.z, x1.z, fmaf(v.w, x1.w, a1))));
            a2 = fmaf(v.x, x2.x, fmaf(v.y, x2.y, fmaf(v.z, x2.z, fmaf(v.w, x2.w, a2))));
            a3 = fmaf(v.x, x3.x, fmaf(v.y, x3.y, fmaf(v.z, x3.z, fmaf(v.w, x3.w, a3))));
        }

        // FSQ quantize: levels (8,8,8,2), strides (1,8,64,512)
        const float acc[4] = {a0, a1, a2, a3};
        const float Lm1[4] = {7.f, 7.f, 7.f, 1.f};
        const int   str[4] = {1, 8, 64, 512};
        float c[4];
        int index = 0;
        #pragma unroll
        for (int j = 0; j < 4; j++) {
            float u = (tanhf(acc[j]) + 1.0f) * 0.5f;
            float s = u * Lm1[j];
            float r = rintf(s);                       // round-half-even == jnp.round
            r = fminf(fmaxf(r, 0.0f), Lm1[j]);
            index += (int)r * str[j];
            c[j] = r - Lm1[j] * 0.5f;
        }

        idx_out[rowBase + lane] = (float)index;       // coalesced STG.32 (plain)
        atomicAdd(&g_hist[index << HPAD], 1);         // 1 bin per 128B line

        sC[warp][lane] = make_float4(c[0], c[1], c[2], c[3]);
    }
    __syncwarp();

    // ---- stage out (per warp): regenerate outputs, coalesced, PLAIN STG ----
    // f = lane + 32*i: column group f&15 == lane&15 (constant), row f>>4 varies.
    {
        const int cgrp = lane & 15;
        const float4 q0 = Wout4[4 * cgrp + 0];
        const float4 q1 = Wout4[4 * cgrp + 1];
        const float4 q2 = Wout4[4 * cgrp + 2];
        const float4 q3 = Wout4[4 * cgrp + 3];

        float4* gout = reinterpret_cast<float4*>(zq) + (size_t)rowBase * 16;
        #pragma unroll
        for (int i = 0; i < 16; i++) {
            int f = lane + i * 32;
            int r = f >> 4;
            float4 cr = sC[warp][r];           // broadcast LDS.128 (2 rows/warp)
            float4 o;
            o.x = fmaf(cr.x, q0.x, fmaf(cr.y, q0.y, fmaf(cr.z, q0.z, cr.w * q0.w)));
            o.y = fmaf(cr.x, q1.x, fmaf(cr.y, q1.y, fmaf(cr.z, q1.z, cr.w * q1.w)));
            o.z = fmaf(cr.x, q2.x, fmaf(cr.y, q2.y, fmaf(cr.z, q2.z, cr.w * q2.w)));
            o.w = fmaf(cr.x, q3.x, fmaf(cr.y, q3.y, fmaf(cr.z, q3.z, cr.w * q3.w)));
            gout[f] = o;                       // plain STG.128: L2 write-allocate
        }
    }

    // ---- last-block finalize (fused; no second launch) ----
    __threadfence();       // make this thread's hist REDs globally visible
    __syncthreads();       // all warps of this block done + fenced
    if (t == 0) {
        unsigned int v = atomicAdd(&g_done, 1u);
        isLast = (v == gridDim.x - 1);
    }
    __syncthreads();
    if (!isLast) return;

    __threadfence();   // acquire: all blocks' hist atomics visible
    float term = 0.f, nz = 0.f;
    #pragma unroll
    for (int i = t; i < NUM_CODES; i += TPB) {
        int cnt = g_hist[i << HPAD];
        g_hist[i << HPAD] = 0;                        // reset for next replay
        float p = (float)cnt * invB;
        term += p * logf(p + 1e-10f);
        nz   += (cnt > 0) ? 1.0f : 0.0f;
    }
    #pragma unroll
    for (int o = 16; o > 0; o >>= 1) {
        term += __shfl_down_sync(0xFFFFFFFFu, term, o);
        nz   += __shfl_down_sync(0xFFFFFFFFu, nz, o);
    }
    if ((t & 31) == 0) { red[t >> 5] = term; red[4 + (t >> 5)] = nz; }
    __syncthreads();
    if (t == 0) {
        float s = red[0] + red[1] + red[2] + red[3];
        float n = red[4] + red[5] + red[6] + red[7];
        scal[0] = 0.0f;                  // commitment_loss
        scal[1] = 0.0f;                  // codebook_loss
        scal[2] = expf(-s);              // perplexity
        scal[3] = n * (1.0f / 1024.0f);  // utilization
        g_done = 0;                      // reset for next replay
    }
}

// ---------------------------------------------------------------------------
extern "C" void kernel_launch(void* const* d_in, const int* in_sizes, int n_in,
                              void* d_out, int out_size) {
    const float* ze   = (const float*)d_in[0];  // (B, 64)
    const float* Win  = (const float*)d_in[1];  // (4, 64)
    const float* Wout = (const float*)d_in[2];  // (64, 4)

    const int B = in_sizes[0] / 64;
    float* out  = (float*)d_out;
    float* zq   = out;                       // B*64
    float* idxf = out + (size_t)B * 64;      // B
    float* scal = idxf + B;                  // 4 scalars

    const int grid = B / TPB;                // 524288 / 128 = 4096

    fsq_main<<<grid, TPB>>>(ze, Win, (const float4*)Wout,
                            zq, idxf, scal, 1.0f / (float)B);
}